// round 14
// baseline (speedup 1.0000x reference)
#include <cuda_runtime.h>

// BKT_RNN: B=8192, T=2048, H=4, X=1.
// R14: R11 base (4 lanes/row, 8 rows/warp, 1024 one-warp blocks, redundant
// packed-f32x2 tau cycle, tau-form tanh sigmoids, fused loss) with the
// latent recurrence DE-SERIALIZED: R11 computed
//     res = fma(hi2 ? latc : lat, ...)  with latc = shfl(lat)
// putting shfl(26)+SEL on the latent cycle of EVERY lane. Now:
//     res_l = fma(lat,  coef, base)   // local cycle: 4 cyc (lanes 0,1)
//     res_c = fma(latc, coef, base)   // shfl-fed, off-cycle (lanes 2,3)
// and the select happens on the output side only.

#define TT 2048
#define BB 8192
#define NBLK (BB / 8)   // 1024 one-warp blocks

typedef unsigned long long u64;

__device__ float    g_part[NBLK];
__device__ unsigned g_done = 0;

__device__ __forceinline__ float lg2f(float v) {
    float r; asm("lg2.approx.f32 %0, %1;" : "=f"(r) : "f"(v)); return r;
}
__device__ __forceinline__ float tanhf_a(float v) {
    float r; asm("tanh.approx.f32 %0, %1;" : "=f"(r) : "f"(v)); return r;
}
__device__ __forceinline__ u64 pack2(float lo, float hi) {
    u64 r; asm("mov.b64 %0, {%1, %2};" : "=l"(r) : "f"(lo), "f"(hi)); return r;
}
__device__ __forceinline__ void unpack2(u64 v, float& lo, float& hi) {
    asm("mov.b64 {%0, %1}, %2;" : "=f"(lo), "=f"(hi) : "l"(v));
}
__device__ __forceinline__ u64 fma2(u64 a, u64 b, u64 c) {
    u64 d; asm("fma.rn.f32x2 %0, %1, %2, %3;" : "=l"(d) : "l"(a), "l"(b), "l"(c));
    return d;
}
__device__ __forceinline__ u64 mul2(u64 a, u64 b) {
    u64 d; asm("mul.rn.f32x2 %0, %1, %2;" : "=l"(d) : "l"(a), "l"(b));
    return d;
}
__device__ __forceinline__ u64 add2(u64 a, u64 b) {
    u64 d; asm("add.rn.f32x2 %0, %1, %2;" : "=l"(d) : "l"(a), "l"(b));
    return d;
}

__global__ void __launch_bounds__(32) k_bkt(
    const float* __restrict__ x,   const float* __restrict__ y,
    const float* __restrict__ Wxh, const float* __restrict__ Whh,
    const float* __restrict__ bh,  const float* __restrict__ Wy,
    const float* __restrict__ by,  const float* __restrict__ prior,
    float* __restrict__ corrects,  float* __restrict__ latents,
    float* __restrict__ loss)
{
    const unsigned FULL = 0xffffffffu;
    const int lane = threadIdx.x;
    const int j = lane & 3;                    // p-unit owned by this lane
    const int b = blockIdx.x * 8 + (lane >> 2);

    // tau-form setup: tau_i = tanh(zh_i/2), h_i = 0.5 + 0.5*tau_i.
    // zh_i/2 = 0.5 x Wxh[i] + sum_m tau_m (Whh[m][i]/4)
    //          + (0.5 bh[i] + 0.25 sum_m Whh[m][i])
    // zp_j/2 = sum_m tau_m (Wy[m][j]/4) + (0.5 by[j] + 0.25 sum_m Wy[m][j])
    float wh[4][4], pre_b[4], xw[4];
    #pragma unroll
    for (int i = 0; i < 4; i++) {
        float s = 0.f;
        #pragma unroll
        for (int m = 0; m < 4; m++) {
            const float w = __ldg(Whh + m * 4 + i);
            wh[m][i] = 0.25f * w;
            s += w;
        }
        pre_b[i] = 0.5f * __ldg(bh + i) + 0.25f * s;
        xw[i]    = 0.5f * __ldg(Wxh + i);
    }
    u64 W01[4], W23[4];
    #pragma unroll
    for (int m = 0; m < 4; m++) {
        W01[m] = pack2(wh[m][0], wh[m][1]);
        W23[m] = pack2(wh[m][2], wh[m][3]);
    }
    const u64 B01  = pack2(pre_b[0], pre_b[1]);
    const u64 B23  = pack2(pre_b[2], pre_b[3]);
    const u64 XW01 = pack2(xw[0], xw[1]);
    const u64 XW23 = pack2(xw[2], xw[3]);

    float Pc[4]; float sWy = 0.f;              // own p column
    #pragma unroll
    for (int m = 0; m < 4; m++) {
        const float w = __ldg(Wy + m * 4 + j);
        Pc[m] = 0.25f * w;
        sWy  += w;
    }
    const float bias_p = 0.5f * __ldg(by + j) + 0.25f * sWy;

    float tau0 = -1.f, tau1 = -1.f, tau2 = -1.f, tau3 = -1.f;  // h = 0
    float lat  = __ldg(prior);     // local recurrence (valid on lanes 0,1)
    float lsum = 0.f;
    const bool odd = (lane & 1) != 0;
    const bool hi2 = (lane & 2) != 0;          // lanes 2,3 -> correct series

    const float4* xp = (const float4*)(x + (size_t)b * TT);
    const float4* yp = (const float4*)(y + (size_t)b * TT);
    float4* op = (float4*)((hi2 ? corrects : latents) + (size_t)b * TT);

    float4 xa = __ldcs(xp + 0), xb = __ldcs(xp + 1);
    float4 ya = __ldcs(yp + 0), yb = __ldcs(yp + 1);

    const int NCHUNK = TT / 8;
    for (int c = 0; c < NCHUNK; ++c) {
        float xv[8] = {xa.x, xa.y, xa.z, xa.w, xb.x, xb.y, xb.z, xb.w};
        float yv[8] = {ya.x, ya.y, ya.z, ya.w, yb.x, yb.y, yb.z, yb.w};

        if (c + 1 < NCHUNK) {
            xa = __ldcs(xp + 2 * c + 2); xb = __ldcs(xp + 2 * c + 3);
            ya = __ldcs(yp + 2 * c + 2); yb = __ldcs(yp + 2 * c + 3);
        }

        float rb[8];
        float prod = 1.f;

        #pragma unroll
        for (int k = 0; k < 8; k++) {
            // ---- x preamble (off the recurrent cycle) ----
            const u64 X2    = pack2(xv[k], xv[k]);
            const u64 PRE01 = fma2(X2, XW01, B01);
            const u64 PRE23 = fma2(X2, XW23, B23);

            // ---- duplicate taus for packed dots ----
            const u64 T0 = pack2(tau0, tau0);
            const u64 T1 = pack2(tau1, tau1);
            const u64 T2 = pack2(tau2, tau2);
            const u64 T3 = pack2(tau3, tau3);

            // ---- packed h pre-activations (all 4 units, this lane) ----
            const u64 Z01 = add2(fma2(T1, W01[1], fma2(T0, W01[0], PRE01)),
                                 fma2(T3, W01[3], mul2(T2, W01[2])));
            const u64 Z23 = add2(fma2(T1, W23[1], fma2(T0, W23[0], PRE23)),
                                 fma2(T3, W23[3], mul2(T2, W23[2])));

            // ---- own p pre-activation (OLD taus) ----
            const float zp = fmaf(tau1, Pc[1], fmaf(tau0, Pc[0], bias_p)) +
                             fmaf(tau3, Pc[3], tau2 * Pc[2]);
            const float taup = tanhf_a(zp);     // p_j = 0.5 + 0.5*taup

            // ---- advance tau (the recurrent cycle) ----
            float z0, z1, z2, z3;
            unpack2(Z01, z0, z1);
            unpack2(Z23, z2, z3);
            tau0 = tanhf_a(z0);
            tau1 = tanhf_a(z1);
            tau2 = tanhf_a(z2);
            tau3 = tanhf_a(z3);

            // ---- latent / correct (tau-form), DE-SERIALIZED ----
            // lanes 0,1 (l,f): lat' = base + lat*coef  (pure local 4-cyc)
            // lanes 2,3 (g,s): correct = base + latc*coef (shfl-fed, off-cycle)
            const float taupo = __shfl_xor_sync(FULL, taup, 1);
            const float coef  = -0.5f * (taup + taupo);
            const float btau  = odd ? taupo : taup;
            const float base  = fmaf(0.5f, btau, 0.5f);
            const float latc  = __shfl_sync(FULL, lat, 0, 4);  // old lat
            const float res_l = fmaf(lat,  coef, base);  // local recurrence
            const float res_c = fmaf(latc, coef, base);  // correct (2,3)
            lat = res_l;                  // meaningful on lanes 0,1
            const float res = hi2 ? res_c : res_l;       // output-side select
            rb[k] = res;

            // ---- loss (lanes 2,3; y in {0,1} -> one factor) ----
            const float cc = fminf(fmaxf(res, 1e-7f), 1.0f - 1e-7f);
            prod *= (yv[k] != 0.f) ? cc : (1.f - cc);
            if ((k & 3) == 3) {
                lsum += hi2 ? lg2f(prod) : 0.f;
                prod = 1.f;
            }
        }

        const float4 v = odd ? make_float4(rb[4], rb[5], rb[6], rb[7])
                             : make_float4(rb[0], rb[1], rb[2], rb[3]);
        __stcs(op + 2 * c + (odd ? 1 : 0), v);
    }

    // Warp reduce (each row counted 2x: lanes 2,3) -> per-block slot.
    #pragma unroll
    for (int o = 16; o > 0; o >>= 1)
        lsum += __shfl_xor_sync(FULL, lsum, o);
    if (lane == 0)
        g_part[blockIdx.x] = lsum;
    __threadfence();

    // Last-block-done loss finalize.
    unsigned ticket = 0;
    if (lane == 0) ticket = atomicAdd(&g_done, 1u);
    ticket = __shfl_sync(FULL, ticket, 0);
    if (ticket == NBLK - 1) {
        double acc = 0.0;
        for (int i = lane; i < NBLK; i += 32)
            acc += (double)g_part[i];
        #pragma unroll
        for (int o = 16; o > 0; o >>= 1)
            acc += __shfl_xor_sync(FULL, acc, o);
        if (lane == 0) {
            loss[0] = (float)(-0.6931471805599453 * acc /
                              (2.0 * (double)BB * (double)TT));
            g_done = 0;   // re-arm for graph replay
        }
    }
}

extern "C" void kernel_launch(void* const* d_in, const int* in_sizes, int n_in,
                              void* d_out, int out_size) {
    const float* x     = (const float*)d_in[0];
    const float* y     = (const float*)d_in[1];
    const float* Wxh   = (const float*)d_in[2];
    const float* Whh   = (const float*)d_in[3];
    const float* bh    = (const float*)d_in[4];
    const float* Wy    = (const float*)d_in[5];
    const float* by    = (const float*)d_in[6];
    const float* prior = (const float*)d_in[7];

    float* corrects = (float*)d_out;
    float* latents  = (float*)d_out + (size_t)BB * TT;
    float* loss     = (float*)d_out + 2 * (size_t)BB * TT;

    k_bkt<<<NBLK, 32>>>(x, y, Wxh, Whh, bh, Wy, by, prior,
                        corrects, latents, loss);
}